// round 11
// baseline (speedup 1.0000x reference)
#include <cuda_runtime.h>

#define NTOK 512
#define DSTATE 192
#define HID 512
#define EMB 1024
#define NEMB 32
#define KC 256   // K rows per warpgroup (HID / 2)
#define CHT 24   // tokens per chunk (P <= 12 pairs)
#define HSS 28   // hs row stride (floats), 16B-aligned rows
#define XSS 28   // xs row stride (floats)

// dynamic smem layout (floats)
#define F_HS0   0
#define F_HS1   (KC * HSS)            // 7168
#define F_XS    (2 * KC * HSS)        // 14336
#define F_FEND  (F_XS + 64 * XSS)     // 16128 floats
// int section starts at byte 4*F_FEND
#define I_TOK   0                     // 512 ints
#define I_START 512                   // 34 ints (pad)
#define I_WCNT  546                   // 16*NEMB = 512
#define I_WOFF  1058                  // 512
#define I_END   1570
#define SMEM_BYTES (4 * F_FEND + 4 * I_END)   // 70792 B

struct Params {
    const float* W1[4];
    const float* b1[4];
    const float* W2[4];
    const float* b2[4];
    const float* te[4];
};

__device__ __forceinline__ void fma2(unsigned long long& acc,
                                     unsigned long long h2,
                                     unsigned long long w2) {
    asm("fma.rn.f32x2 %0, %1, %2, %0;" : "+l"(acc) : "l"(h2), "l"(w2));
}
__device__ __forceinline__ unsigned long long splat2(float v) {
    unsigned long long r;
    asm("mov.b64 %0, {%1,%1};" : "=l"(r) : "r"(__float_as_uint(v)));
    return r;
}

#define WD 8  // W2 prefetch group size (LDG.64 each -> 16 lines/warp)

template <int P>
__device__ __forceinline__ void consume(const float2* w, const float* hs, int g,
                                        unsigned long long* a0, unsigned long long* a1) {
    #pragma unroll
    for (int j = 0; j < WD; j++) {
        unsigned long long w0 = splat2(w[j].x);
        unsigned long long w1 = splat2(w[j].y);
        const float* hrow = hs + (g + j) * HSS;
        #pragma unroll
        for (int p2 = 0; p2 < P / 2; p2++) {
            ulonglong2 hv = *(const ulonglong2*)(hrow + 4 * p2); // LDS.128 bcast
            fma2(a0[2 * p2],     hv.x, w0);
            fma2(a0[2 * p2 + 1], hv.y, w0);
            fma2(a1[2 * p2],     hv.x, w1);
            fma2(a1[2 * p2 + 1], hv.y, w1);
        }
    }
}

template <int P, int L, int OFF>  // P even 2..12 token pairs
__device__ __forceinline__ void run_chunk(
    float* hs_my, float* red, float* xs, const int* s_tokens,
    const float* __restrict__ state,
    const float* __restrict__ W1ec, float2 b1v,
    const float* __restrict__ W2ec,
    float2 init, int s0cb, int rem, int wtid, int wg, int c0, int m,
    float* __restrict__ out)
{
    int tid = threadIdx.x;

    // ---- gather x (2P tokens, clamped pad) transposed into shared xs ----
    __syncthreads();
    #pragma unroll 1
    for (int idx = tid; idx < 2 * P * L; idx += 256) {
        int tk = idx / L, l = idx - tk * L;
        int tok = s_tokens[min(s0cb + tk, NTOK - 1)];
        xs[l * XSS + tk] = state[tok * DSTATE + OFF + l];
    }
    __syncthreads();

    {   // ---- h = relu(x . W1half + b1) for hs_my rows {2*wtid, 2*wtid+1} ----
        unsigned long long hA[P], hB[P];
        unsigned long long bA = splat2(b1v.x), bB = splat2(b1v.y);
        #pragma unroll
        for (int p = 0; p < P; p++) { hA[p] = bA; hB[p] = bB; }

        #pragma unroll 1
        for (int l0 = 0; l0 < L; l0 += 8) {
            float2 w[8];
            #pragma unroll
            for (int u = 0; u < 8; u++)
                w[u] = *(const float2*)(W1ec + (size_t)(l0 + u) * HID);
            #pragma unroll
            for (int u = 0; u < 8; u++) {
                unsigned long long w0 = splat2(w[u].x);
                unsigned long long w1 = splat2(w[u].y);
                const float* xrow = xs + (l0 + u) * XSS;
                #pragma unroll
                for (int p2 = 0; p2 < P / 2; p2++) {
                    ulonglong2 xv = *(const ulonglong2*)(xrow + 4 * p2);
                    fma2(hA[2 * p2],     xv.x, w0);
                    fma2(hA[2 * p2 + 1], xv.y, w0);
                    fma2(hB[2 * p2],     xv.x, w1);
                    fma2(hB[2 * p2 + 1], xv.y, w1);
                }
            }
        }
        float* rowA = hs_my + (2 * wtid) * HSS;
        float* rowB = hs_my + (2 * wtid + 1) * HSS;
        #pragma unroll
        for (int p = 0; p < P; p++) {
            float2 a = *(float2*)&hA[p];
            float2 b = *(float2*)&hB[p];
            a.x = fmaxf(a.x, 0.f); a.y = fmaxf(a.y, 0.f);
            b.x = fmaxf(b.x, 0.f); b.y = fmaxf(b.y, 0.f);
            *(float2*)&rowA[2 * p] = a;
            *(float2*)&rowB[2 * p] = b;
        }
    }
    __syncthreads();

    // ---- mainloop: W2 half stream, double-buffered ----
    unsigned long long a0[P], a1[P];
    unsigned long long i0 = splat2(init.x), i1 = splat2(init.y);
    #pragma unroll
    for (int p = 0; p < P; p++) { a0[p] = i0; a1[p] = i1; }

    float2 wA[WD], wB[WD];
    #pragma unroll
    for (int j = 0; j < WD; j++)
        wA[j] = __ldcs((const float2*)(W2ec + (size_t)j * EMB));

    #pragma unroll 1
    for (int g = 0; g < KC - 2 * WD; g += 2 * WD) {
        #pragma unroll
        for (int j = 0; j < WD; j++)
            wB[j] = __ldcs((const float2*)(W2ec + (size_t)(g + WD + j) * EMB));
        consume<P>(wA, hs_my, g, a0, a1);
        #pragma unroll
        for (int j = 0; j < WD; j++)
            wA[j] = __ldcs((const float2*)(W2ec + (size_t)(g + 2 * WD + j) * EMB));
        consume<P>(wB, hs_my, g + WD, a0, a1);
    }
    #pragma unroll
    for (int j = 0; j < WD; j++)
        wB[j] = __ldcs((const float2*)(W2ec + (size_t)(KC - WD + j) * EMB));
    consume<P>(wA, hs_my, KC - 2 * WD, a0, a1);
    consume<P>(wB, hs_my, KC - WD, a0, a1);

    // ---- cross-warpgroup reduction + direct output ----
    constexpr int RSTR = 4 * P + 4;  // padded stride (odd /4 -> bank spread)
    if (wg == 1) {
        // kh1 parks partials in its own (now-dead) hs buffer
        #pragma unroll
        for (int p = 0; p < P; p++) {
            float2 vA = *(float2*)&a0[p];
            float2 vB = *(float2*)&a1[p];
            *(float4*)&red[wtid * RSTR + 4 * p] = make_float4(vA.x, vA.y, vB.x, vB.y);
        }
    }
    __syncthreads();
    if (wg == 0) {
        #pragma unroll
        for (int p = 0; p < P; p++) {
            float2 vA = *(float2*)&a0[p]; // col c0:   (tok 2p, tok 2p+1)
            float2 vB = *(float2*)&a1[p]; // col c0+1
            float4 r = *(const float4*)&red[wtid * RSTR + 4 * p];
            int t0 = 2 * p;
            if (t0 < rem) {
                int tok = s_tokens[s0cb + t0];
                *(float2*)&out[((size_t)tok * 4 + m) * EMB + c0]
                    = make_float2(vA.x + r.x, vB.x + r.z);
            }
            if (t0 + 1 < rem) {
                int tok = s_tokens[s0cb + t0 + 1];
                *(float2*)&out[((size_t)tok * 4 + m) * EMB + c0]
                    = make_float2(vA.y + r.y, vB.y + r.w);
            }
        }
    }
}

template <int L, int OFF>
__device__ __forceinline__ void mega_body(
    const Params& p, const float* __restrict__ state, float* __restrict__ out,
    int m, int e, int tile, float* smf, int* smi)
{
    int tid  = threadIdx.x;
    int wg   = tid >> 7;        // warpgroup = k-half
    int wtid = tid & 127;

    const int* s_tokens = smi + I_TOK;
    const int* s_start  = smi + I_START;
    int s0 = s_start[e];
    int n  = s_start[e + 1] - s0;
    if (n == 0) return;

    float* hs_my = smf + (wg ? F_HS1 : F_HS0);
    float* red   = smf + F_HS1;
    float* xs    = smf + F_XS;

    int c0 = tile * 256 + wtid * 2;
    int j0 = wg * KC + 2 * wtid;
    const float* W2ec = p.W2[m] + (size_t)e * HID * EMB + (size_t)wg * KC * EMB + c0;
    const float* W1ec = p.W1[m] + (size_t)e * L * HID + j0;
    float2 b1v = *(const float2*)&p.b1[m][e * HID + j0];
    float2 init = (wg == 0)
        ? make_float2(p.b2[m][e * EMB + c0]     + p.te[m][c0],
                      p.b2[m][e * EMB + c0 + 1] + p.te[m][c0 + 1])
        : make_float2(0.f, 0.f);

    for (int cb = 0; cb < n; cb += CHT) {
        int rem = min(n - cb, CHT);
        int pairsEven = ((rem + 3) >> 2) << 1; // even ceil(rem/2)
        int s0cb = s0 + cb;
        switch (pairsEven) {
#define CASE(PP) case PP: run_chunk<PP, L, OFF>(hs_my, red, xs, s_tokens, state, \
                          W1ec, b1v, W2ec, init, s0cb, rem, wtid, wg, c0, m, out); break;
            CASE(2) CASE(4) CASE(6) CASE(8) CASE(10) CASE(12)
#undef CASE
        }
    }
}

__global__ void __launch_bounds__(256) k_mega(Params p,
                                              const float* __restrict__ state,
                                              const int* __restrict__ ids_raw,
                                              float* __restrict__ out) {
    extern __shared__ float smf[];
    int* smi = (int*)(smf + F_FEND);

    int tid  = threadIdx.x;           // 256
    int warp = tid >> 5, lane = tid & 31;

    // ---- deterministic in-block grouping (identical in every block) ----
    int* s_tokens = smi + I_TOK;
    int* s_start  = smi + I_START;
    int* s_wcnt   = smi + I_WCNT;
    int* s_woff   = smi + I_WOFF;
    __shared__ int s_i64;

    s_wcnt[tid] = 0;
    s_wcnt[tid + 256] = 0;
    if (tid == 0) s_i64 = 1;
    __syncthreads();
    // int64 ids (<32) have zero high words at odd int32 indices.
    if (ids_raw[2 * tid + 1] != 0) s_i64 = 0;
    __syncthreads();
    int tA = tid, tB = tid + 256;
    int cA = s_i64 ? ids_raw[2 * tA] : ids_raw[tA];
    int cB = s_i64 ? ids_raw[2 * tB] : ids_raw[tB];

    unsigned sameA = __match_any_sync(0xffffffffu, cA);
    int rankA = __popc(sameA & ((1u << lane) - 1u));
    if (rankA == 0) s_wcnt[warp * NEMB + cA] = __popc(sameA);
    unsigned sameB = __match_any_sync(0xffffffffu, cB);
    int rankB = __popc(sameB & ((1u << lane) - 1u));
    if (rankB == 0) s_wcnt[(8 + warp) * NEMB + cB] = __popc(sameB);
    __syncthreads();

    if (tid < NEMB) {
        int sum = 0;
        #pragma unroll
        for (int w = 0; w < 16; w++) {
            int c = s_wcnt[w * NEMB + tid];
            s_woff[w * NEMB + tid] = sum;
            sum += c;
        }
        s_wcnt[tid] = sum; // total per id
    }
    __syncthreads();
    if (tid <= NEMB) {
        int s = 0;
        for (int j = 0; j < tid && j < NEMB; j++) s += s_wcnt[j];
        s_start[tid] = s;
    }
    __syncthreads();

    s_tokens[s_start[cA] + s_woff[warp * NEMB + cA] + rankA] = tA;
    s_tokens[s_start[cB] + s_woff[(8 + warp) * NEMB + cB] + rankB] = tB;
    __syncthreads();

    // ---- fused MLP + output ----
    int tile = blockIdx.x;  // 0..3 (256 cols each)
    int m    = blockIdx.y;  // 0..3
    int e    = blockIdx.z;  // 0..31

    switch (m) {
        case 0: mega_body<64, 0  >(p, state, out, 0, e, tile, smf, smi); break;
        case 1: mega_body<64, 64 >(p, state, out, 1, e, tile, smf, smi); break;
        case 2: mega_body<32, 128>(p, state, out, 2, e, tile, smf, smi); break;
        case 3: mega_body<32, 160>(p, state, out, 3, e, tile, smf, smi); break;
    }
}

// ---------------------------------------------------------------------------
extern "C" void kernel_launch(void* const* d_in, const int* in_sizes, int n_in,
                              void* d_out, int out_size) {
    const float* state = (const float*)d_in[0];
    const int*   ids   = (const int*)d_in[1];

    Params P;
    int base = 2;
    for (int m = 0; m < 4; m++) {
        P.W1[m] = (const float*)d_in[base + 0];
        P.b1[m] = (const float*)d_in[base + 1];
        P.W2[m] = (const float*)d_in[base + 2];
        P.b2[m] = (const float*)d_in[base + 3];
        P.te[m] = (const float*)d_in[base + 4];
        base += 5;
    }
    float* out = (float*)d_out;

    // host-side attribute set (idempotent, not a stream op -> capture-safe)
    cudaFuncSetAttribute(k_mega, cudaFuncAttributeMaxDynamicSharedMemorySize,
                         SMEM_BYTES);

    k_mega<<<dim3(4, 4, 32), 256, SMEM_BYTES>>>(P, state, ids, out);
}

// round 12
// speedup vs baseline: 1.3230x; 1.3230x over previous
#include <cuda_runtime.h>

#define NTOK 512
#define DSTATE 192
#define HID 512
#define EMB 1024
#define NEMB 32
#define KC 256   // K rows per stage2 block (HID / 2 k-halves)
#define CHT 24   // tokens per stage2 chunk (P <= 12 pairs)
#define HSS 28   // smem row stride (floats): 112 B rows, 16B-aligned

// scratch (allocs forbidden -> device globals)
__device__ int g_start[NEMB + 1];
__device__ int g_tokens[NTOK];
__device__ float g_H[NTOK * 4 * HID];        // [slot][m][HID]
__device__ float g_part[2][4 * NTOK * EMB];  // [kh][m][slot][EMB]

struct Params {
    const float* W1[4];
    const float* b1[4];
    const float* W2[4];
    const float* b2[4];
    const float* te[4];
};

// ---------------------------------------------------------------------------
// Stage 1: grid (jhalf 2, m 4, e 32) = 256 blocks x 256 threads.
// Each block re-derives the token grouping (deterministic match/histogram,
// input-only -> identical in every block); block (0,0,0) publishes it.
// Then H[slot][m][j] = relu(x_m . W1_m[e] + b1_m[e]) for its 256 j-columns.
// ---------------------------------------------------------------------------
template <int L, int OFF>
__device__ __forceinline__ void mlp1(const float* __restrict__ state,
                                     const float* __restrict__ W1,
                                     float b, int m, int j, int s0, int n,
                                     const int* __restrict__ s_tokens,
                                     float* __restrict__ xs) {
    int tid = threadIdx.x; // 256
    for (int cb = 0; cb < n; cb += 16) {
        int rem = min(n - cb, 16);
        __syncthreads();
        for (int idx = tid; idx < 16 * L; idx += 256) {
            int tk = idx / L, l = idx - tk * L;
            float v = 0.f;
            if (tk < rem) {
                int tok = s_tokens[s0 + cb + tk];
                v = state[tok * DSTATE + OFF + l];
            }
            xs[tk * L + l] = v;
        }
        __syncthreads();

        float acc[16];
        #pragma unroll
        for (int t = 0; t < 16; t++) acc[t] = b;

        // unroll 4 -> 32 W1 loads visible per scheduling window (deep MLP)
        #pragma unroll 4
        for (int l0 = 0; l0 < L; l0 += 8) {
            float w[8];
            #pragma unroll
            for (int u = 0; u < 8; u++)
                w[u] = W1[(l0 + u) * HID + j];
            #pragma unroll
            for (int u = 0; u < 8; u++) {
                #pragma unroll
                for (int t = 0; t < 16; t++)
                    acc[t] = fmaf(xs[t * L + l0 + u], w[u], acc[t]);
            }
        }

        #pragma unroll
        for (int t = 0; t < 16; t++) {
            if (t < rem)
                g_H[((size_t)(s0 + cb + t) * 4 + m) * HID + j] = fmaxf(acc[t], 0.f);
        }
        __syncthreads();
    }
}

__global__ void __launch_bounds__(256) k_stage1(const float* __restrict__ state,
                                                const int* __restrict__ ids_raw,
                                                Params p) {
    __shared__ int s_start[NEMB + 2];
    __shared__ int s_tokens[NTOK];
    __shared__ int s_wcnt[16 * NEMB];
    __shared__ int s_woff[16 * NEMB];
    __shared__ int s_i64;
    __shared__ float xs[16 * 64];

    int tid  = threadIdx.x; // 256
    int warp = tid >> 5, lane = tid & 31;

    s_wcnt[tid] = 0;
    s_wcnt[tid + 256] = 0;
    if (tid == 0) s_i64 = 1;
    __syncthreads();
    // int64 ids (<32) have zero high words at odd int32 indices.
    if (ids_raw[2 * tid + 1] != 0) s_i64 = 0;
    __syncthreads();
    int tA = tid, tB = tid + 256;
    int cA = s_i64 ? ids_raw[2 * tA] : ids_raw[tA];
    int cB = s_i64 ? ids_raw[2 * tB] : ids_raw[tB];

    unsigned sameA = __match_any_sync(0xffffffffu, cA);
    int rankA = __popc(sameA & ((1u << lane) - 1u));
    if (rankA == 0) s_wcnt[warp * NEMB + cA] = __popc(sameA);
    unsigned sameB = __match_any_sync(0xffffffffu, cB);
    int rankB = __popc(sameB & ((1u << lane) - 1u));
    if (rankB == 0) s_wcnt[(8 + warp) * NEMB + cB] = __popc(sameB);
    __syncthreads();

    if (tid < NEMB) {
        int sum = 0;
        #pragma unroll
        for (int w = 0; w < 16; w++) {
            int c = s_wcnt[w * NEMB + tid];
            s_woff[w * NEMB + tid] = sum;
            sum += c;
        }
        s_wcnt[tid] = sum; // total per id
    }
    __syncthreads();
    if (tid <= NEMB) {
        int s = 0;
        for (int jj = 0; jj < tid && jj < NEMB; jj++) s += s_wcnt[jj];
        s_start[tid] = s;
    }
    __syncthreads();

    s_tokens[s_start[cA] + s_woff[warp * NEMB + cA] + rankA] = tA;
    s_tokens[s_start[cB] + s_woff[(8 + warp) * NEMB + cB] + rankB] = tB;
    __syncthreads();

    if (blockIdx.x == 0 && blockIdx.y == 0 && blockIdx.z == 0) {
        if (tid <= NEMB) g_start[tid] = s_start[tid];
        g_tokens[tA] = s_tokens[tA];
        g_tokens[tB] = s_tokens[tB];
    }

    // ---- per-block MLP: (jh, m, e) ----
    int jh = blockIdx.x;       // 0..1
    int m  = blockIdx.y;       // 0..3
    int e  = blockIdx.z;       // 0..31
    int j  = jh * 256 + tid;

    int s0 = s_start[e];
    int n  = s_start[e + 1] - s0;
    if (n == 0) return;

    float b;
    switch (m) {
        case 0: b = p.b1[0][e * HID + j];
                mlp1<64, 0  >(state, p.W1[0] + (size_t)e * 64 * HID, b, 0, j, s0, n, s_tokens, xs); break;
        case 1: b = p.b1[1][e * HID + j];
                mlp1<64, 64 >(state, p.W1[1] + (size_t)e * 64 * HID, b, 1, j, s0, n, s_tokens, xs); break;
        case 2: b = p.b1[2][e * HID + j];
                mlp1<32, 128>(state, p.W1[2] + (size_t)e * 32 * HID, b, 2, j, s0, n, s_tokens, xs); break;
        case 3: b = p.b1[3][e * HID + j];
                mlp1<32, 160>(state, p.W1[3] + (size_t)e * 32 * HID, b, 3, j, s0, n, s_tokens, xs); break;
    }
}

// ---------------------------------------------------------------------------
// Stage 2 (K-split): part[kh][m][slot][c] = H[slot][m][kh*256:+256] . W2rows.
// Block = (kh, 256-col tile, m, e); thread owns 2 adjacent columns (LDG.64).
// WD=8 double-buffered register pipeline, CHT=24, launch_bounds(128,4).
// (byte-identical to the round-8/9 champion)
// ---------------------------------------------------------------------------
__device__ __forceinline__ void fma2(unsigned long long& acc,
                                     unsigned long long h2,
                                     unsigned long long w2) {
    asm("fma.rn.f32x2 %0, %1, %2, %0;" : "+l"(acc) : "l"(h2), "l"(w2));
}
__device__ __forceinline__ unsigned long long splat2(float v) {
    unsigned long long r;
    asm("mov.b64 %0, {%1,%1};" : "=l"(r) : "r"(__float_as_uint(v)));
    return r;
}

#define WD 8  // W2 prefetch group size (LDG.64 each -> 16 lines/warp)

template <int P>
__device__ __forceinline__ void consume(const float2* w, const float* hs, int g,
                                        unsigned long long* a0, unsigned long long* a1) {
    #pragma unroll
    for (int j = 0; j < WD; j++) {
        unsigned long long w0 = splat2(w[j].x);
        unsigned long long w1 = splat2(w[j].y);
        const float* hrow = hs + (g + j) * HSS;
        #pragma unroll
        for (int p2 = 0; p2 < P / 2; p2++) {
            ulonglong2 hv = *(const ulonglong2*)(hrow + 4 * p2); // LDS.128 bcast
            fma2(a0[2 * p2],     hv.x, w0);
            fma2(a0[2 * p2 + 1], hv.y, w0);
            fma2(a1[2 * p2],     hv.x, w1);
            fma2(a1[2 * p2 + 1], hv.y, w1);
        }
    }
}

template <int P>  // P even, 2..12: token pairs in flight
__device__ __forceinline__ void run_chunk(
    float* hs, const float* __restrict__ W2ec, const float* __restrict__ Hme,
    float2 init, int s0cb, int rem, int tid, int c0,
    float* __restrict__ pm)
{
    unsigned long long a0[P], a1[P];
    unsigned long long i0 = splat2(init.x), i1 = splat2(init.y);
    #pragma unroll
    for (int p = 0; p < P; p++) { a0[p] = i0; a1[p] = i1; }

    __syncthreads();
    // stage h transposed: hs[kk*HSS + tk], tk in [0, 2P); Hme pre-offset kh*KC
    #pragma unroll
    for (int tk = 0; tk < 2 * P; tk++) {
        int slot = min(s0cb + tk, NTOK - 1); // clamp pad (discarded later)
        const float* src = Hme + (size_t)slot * (4 * HID);
        #pragma unroll
        for (int kk = 0; kk < KC; kk += 128)
            hs[(kk + tid) * HSS + tk] = src[kk + tid];
    }
    __syncthreads();

    float2 wA[WD], wB[WD];
    #pragma unroll
    for (int j = 0; j < WD; j++)
        wA[j] = __ldcs((const float2*)(W2ec + (size_t)j * EMB));

    #pragma unroll 1
    for (int g = 0; g < KC - 2 * WD; g += 2 * WD) {
        #pragma unroll
        for (int j = 0; j < WD; j++)
            wB[j] = __ldcs((const float2*)(W2ec + (size_t)(g + WD + j) * EMB));
        consume<P>(wA, hs, g, a0, a1);
        #pragma unroll
        for (int j = 0; j < WD; j++)
            wA[j] = __ldcs((const float2*)(W2ec + (size_t)(g + 2 * WD + j) * EMB));
        consume<P>(wB, hs, g + WD, a0, a1);
    }
    #pragma unroll
    for (int j = 0; j < WD; j++)
        wB[j] = __ldcs((const float2*)(W2ec + (size_t)(KC - WD + j) * EMB));
    consume<P>(wA, hs, KC - 2 * WD, a0, a1);
    consume<P>(wB, hs, KC - WD, a0, a1);

    #pragma unroll
    for (int p = 0; p < P; p++) {
        float2 vA = *(float2*)&a0[p]; // col c0:   (tok 2p, tok 2p+1)
        float2 vB = *(float2*)&a1[p]; // col c0+1
        int t0 = 2 * p;
        if (t0 < rem) {
            int slot = s0cb + t0;
            *(float2*)&pm[(size_t)slot * EMB + c0] = make_float2(vA.x, vB.x);
        }
        if (t0 + 1 < rem) {
            int slot = s0cb + t0 + 1;
            *(float2*)&pm[(size_t)slot * EMB + c0] = make_float2(vA.y, vB.y);
        }
    }
}

__global__ void __launch_bounds__(128, 4) k_stage2(Params p) {
    int bx   = blockIdx.x;     // 0..7 = tile(0..3) | kh<<2
    int tile = bx & 3;
    int kh   = bx >> 2;        // k-half: W2 rows [kh*256, +256)
    int m    = blockIdx.y;     // 0..3
    int e    = blockIdx.z;     // 0..31
    int s0 = g_start[e];
    int n  = g_start[e + 1] - s0;
    if (n == 0) return;

    int tid = threadIdx.x;
    int c0 = tile * 256 + tid * 2;
    const float* __restrict__ W2ec = p.W2[m] + (size_t)e * HID * EMB
                                   + (size_t)kh * KC * EMB + c0;
    const float* __restrict__ Hme  = g_H + m * HID + kh * KC;
    float2 init = (kh == 0)
        ? make_float2(p.b2[m][e * EMB + c0]     + p.te[m][c0],
                      p.b2[m][e * EMB + c0 + 1] + p.te[m][c0 + 1])
        : make_float2(0.f, 0.f);
    float* pm = &g_part[kh][(size_t)m * NTOK * EMB];

    __shared__ __align__(16) float hs[KC * HSS];

    for (int cb = 0; cb < n; cb += CHT) {
        int rem = min(n - cb, CHT);
        int pairsEven = ((rem + 3) >> 2) << 1; // even ceil(rem/2)
        int s0cb = s0 + cb;
        switch (pairsEven) {
#define CASE(PP) case PP: run_chunk<PP>(hs, W2ec, Hme, init, s0cb, rem, tid, c0, pm); break;
            CASE(2) CASE(4) CASE(6) CASE(8) CASE(10) CASE(12)
#undef CASE
        }
    }
}

// ---------------------------------------------------------------------------
// Combine: out[tok][m][c] = part0 + part1, gathering slot -> token.
// ---------------------------------------------------------------------------
__global__ void __launch_bounds__(256) k_combine(float* __restrict__ out) {
    int slot = blockIdx.x;
    int m    = blockIdx.y;
    int tid  = threadIdx.x;
    int tok  = g_tokens[slot];
    const float4* p0 = (const float4*)(&g_part[0][0] + ((size_t)m * NTOK + slot) * EMB);
    const float4* p1 = (const float4*)(&g_part[1][0] + ((size_t)m * NTOK + slot) * EMB);
    float4* o = (float4*)(out + ((size_t)tok * 4 + m) * EMB);
    float4 a = p0[tid], b = p1[tid];
    o[tid] = make_float4(a.x + b.x, a.y + b.y, a.z + b.z, a.w + b.w);
}

// ---------------------------------------------------------------------------
extern "C" void kernel_launch(void* const* d_in, const int* in_sizes, int n_in,
                              void* d_out, int out_size) {
    const float* state = (const float*)d_in[0];
    const int*   ids   = (const int*)d_in[1];

    Params P;
    int base = 2;
    for (int m = 0; m < 4; m++) {
        P.W1[m] = (const float*)d_in[base + 0];
        P.b1[m] = (const float*)d_in[base + 1];
        P.W2[m] = (const float*)d_in[base + 2];
        P.b2[m] = (const float*)d_in[base + 3];
        P.te[m] = (const float*)d_in[base + 4];
        base += 5;
    }
    float* out = (float*)d_out;

    k_stage1<<<dim3(2, 4, 32), 256>>>(state, ids, P);
    k_stage2<<<dim3(8, 4, 32), 128>>>(P);
    k_combine<<<dim3(NTOK, 4), 256>>>(out);
}

// round 13
// speedup vs baseline: 1.3632x; 1.0304x over previous
#include <cuda_runtime.h>

#define NTOK 512
#define DSTATE 192
#define HID 512
#define EMB 1024
#define NEMB 32
#define KC 256   // K rows per stage2 block (HID / 2 k-halves)
#define CHT 24   // tokens per stage2 chunk (P <= 12 pairs)
#define HSS 28   // smem row stride (floats): 112 B rows, 16B-aligned
#define CB1 32   // stage1 tokens per chunk (W1 read exactly once per block)

// scratch (allocs forbidden -> device globals)
__device__ int g_start[NEMB + 1];
__device__ int g_tokens[NTOK];
__device__ float g_H[NTOK * 4 * HID];        // [slot][m][HID]
__device__ float g_part[2][4 * NTOK * EMB];  // [kh][m][slot][EMB]

struct Params {
    const float* W1[4];
    const float* b1[4];
    const float* W2[4];
    const float* b2[4];
    const float* te[4];
};

// ---------------------------------------------------------------------------
// Stage 1: 128 blocks = (e,m), 512 threads = one HID column each.
// Grouping re-derived per block (deterministic match/histogram); block 0
// publishes for stage2. W1 stream DOUBLE-BUFFERED (groups of 8 rows) so 8
// lines/warp stay in flight continuously; 32-token chunks -> W1 read once.
// ---------------------------------------------------------------------------
template <int L, int OFF>
__device__ __forceinline__ void mlp1(const float* __restrict__ state,
                                     const float* __restrict__ W1,
                                     float b, int m, int s0, int n,
                                     const int* __restrict__ s_tokens,
                                     float* __restrict__ xs) {
    int j = threadIdx.x;

    #pragma unroll 1
    for (int cb = 0; cb < n; cb += CB1) {
        int rem = min(n - cb, CB1);
        __syncthreads();
        #pragma unroll 1
        for (int idx = j; idx < CB1 * L; idx += 512) {
            int tk = idx / L, l = idx - tk * L;
            float v = 0.f;
            if (tk < rem) {
                int tok = s_tokens[s0 + cb + tk];
                v = state[tok * DSTATE + OFF + l];
            }
            xs[tk * L + l] = v;
        }
        __syncthreads();

        float acc[CB1];
        #pragma unroll
        for (int t = 0; t < CB1; t++) acc[t] = b;

        float wA[8], wB[8];
        #pragma unroll
        for (int u = 0; u < 8; u++) wA[u] = W1[u * HID + j];

        #pragma unroll 1
        for (int g = 0; g < L - 16; g += 16) {
            #pragma unroll
            for (int u = 0; u < 8; u++) wB[u] = W1[(g + 8 + u) * HID + j];
            #pragma unroll
            for (int u = 0; u < 8; u++) {
                float w = wA[u];
                #pragma unroll
                for (int t = 0; t < CB1; t++)
                    acc[t] = fmaf(xs[t * L + g + u], w, acc[t]);
            }
            #pragma unroll
            for (int u = 0; u < 8; u++) wA[u] = W1[(g + 16 + u) * HID + j];
            #pragma unroll
            for (int u = 0; u < 8; u++) {
                float w = wB[u];
                #pragma unroll
                for (int t = 0; t < CB1; t++)
                    acc[t] = fmaf(xs[t * L + g + 8 + u], w, acc[t]);
            }
        }
        // tail: groups L-16 (in wA) and L-8
        #pragma unroll
        for (int u = 0; u < 8; u++) wB[u] = W1[(L - 8 + u) * HID + j];
        #pragma unroll
        for (int u = 0; u < 8; u++) {
            float w = wA[u];
            #pragma unroll
            for (int t = 0; t < CB1; t++)
                acc[t] = fmaf(xs[t * L + (L - 16) + u], w, acc[t]);
        }
        #pragma unroll
        for (int u = 0; u < 8; u++) {
            float w = wB[u];
            #pragma unroll
            for (int t = 0; t < CB1; t++)
                acc[t] = fmaf(xs[t * L + (L - 8) + u], w, acc[t]);
        }

        #pragma unroll
        for (int t = 0; t < CB1; t++) {
            if (t < rem)
                g_H[((size_t)(s0 + cb + t) * 4 + m) * HID + j] = fmaxf(acc[t], 0.f);
        }
        __syncthreads();
    }
}

__global__ void __launch_bounds__(512) k_stage1(const float* __restrict__ state,
                                                const int* __restrict__ ids_raw,
                                                Params p) {
    __shared__ int s_startA[NEMB + 1];
    __shared__ int s_tokens[NTOK];
    __shared__ int s_wcnt[16 * NEMB];
    __shared__ int s_woff[16 * NEMB];
    __shared__ int s_i64;
    __shared__ float xs[CB1 * 64];

    int tid  = threadIdx.x; // 512
    int warp = tid >> 5, lane = tid & 31;

    s_wcnt[tid & (16 * NEMB - 1)] = 0;
    if (tid == 0) s_i64 = 1;
    __syncthreads();
    if (tid < 256 && ids_raw[2 * tid + 1] != 0) s_i64 = 0;
    __syncthreads();
    int myc = s_i64 ? ids_raw[2 * tid] : ids_raw[tid];

    unsigned same = __match_any_sync(0xffffffffu, myc);
    int rankw = __popc(same & ((1u << lane) - 1u));
    if (rankw == 0) s_wcnt[warp * NEMB + myc] = __popc(same);
    __syncthreads();

    if (tid < NEMB) {
        int sum = 0;
        #pragma unroll
        for (int w = 0; w < 16; w++) {
            int ccc = s_wcnt[w * NEMB + tid];
            s_woff[w * NEMB + tid] = sum;
            sum += ccc;
        }
        s_wcnt[tid] = sum; // total per id
    }
    __syncthreads();
    if (tid <= NEMB) {
        int s = 0;
        for (int jj = 0; jj < tid && jj < NEMB; jj++) s += s_wcnt[jj];
        s_startA[tid] = s;
    }
    __syncthreads();

    int slot = s_startA[myc] + s_woff[warp * NEMB + myc] + rankw;
    s_tokens[slot] = tid;
    __syncthreads();

    if (blockIdx.x == 0) {
        if (tid <= NEMB) g_start[tid] = s_startA[tid];
        g_tokens[tid] = s_tokens[tid];
    }

    // ---- per-block MLP
    int m = blockIdx.x & 3;
    int e = blockIdx.x >> 2;
    int s0 = s_startA[e];
    int n  = s_startA[e + 1] - s0;
    if (n == 0) return;

    float b;
    switch (m) {
        case 0: b = p.b1[0][e * HID + tid];
                mlp1<64, 0  >(state, p.W1[0] + (size_t)e * 64 * HID, b, 0, s0, n, s_tokens, xs); break;
        case 1: b = p.b1[1][e * HID + tid];
                mlp1<64, 64 >(state, p.W1[1] + (size_t)e * 64 * HID, b, 1, s0, n, s_tokens, xs); break;
        case 2: b = p.b1[2][e * HID + tid];
                mlp1<32, 128>(state, p.W1[2] + (size_t)e * 32 * HID, b, 2, s0, n, s_tokens, xs); break;
        case 3: b = p.b1[3][e * HID + tid];
                mlp1<32, 160>(state, p.W1[3] + (size_t)e * 32 * HID, b, 3, s0, n, s_tokens, xs); break;
    }
}

// ---------------------------------------------------------------------------
// Stage 2 (K-split): part[kh][m][slot][c] = H[slot][m][kh*256:+256] . W2rows.
// Block = (kh, 256-col tile, m, e); thread owns 2 adjacent columns (LDG.64).
// WD=8 double-buffered register pipeline, CHT=24, launch_bounds(128,4).
// (byte-identical to the round-8/9 champion)
// ---------------------------------------------------------------------------
__device__ __forceinline__ void fma2(unsigned long long& acc,
                                     unsigned long long h2,
                                     unsigned long long w2) {
    asm("fma.rn.f32x2 %0, %1, %2, %0;" : "+l"(acc) : "l"(h2), "l"(w2));
}
__device__ __forceinline__ unsigned long long splat2(float v) {
    unsigned long long r;
    asm("mov.b64 %0, {%1,%1};" : "=l"(r) : "r"(__float_as_uint(v)));
    return r;
}

#define WD 8  // W2 prefetch group size (LDG.64 each -> 16 lines/warp)

template <int P>
__device__ __forceinline__ void consume(const float2* w, const float* hs, int g,
                                        unsigned long long* a0, unsigned long long* a1) {
    #pragma unroll
    for (int j = 0; j < WD; j++) {
        unsigned long long w0 = splat2(w[j].x);
        unsigned long long w1 = splat2(w[j].y);
        const float* hrow = hs + (g + j) * HSS;
        #pragma unroll
        for (int p2 = 0; p2 < P / 2; p2++) {
            ulonglong2 hv = *(const ulonglong2*)(hrow + 4 * p2); // LDS.128 bcast
            fma2(a0[2 * p2],     hv.x, w0);
            fma2(a0[2 * p2 + 1], hv.y, w0);
            fma2(a1[2 * p2],     hv.x, w1);
            fma2(a1[2 * p2 + 1], hv.y, w1);
        }
    }
}

template <int P>  // P even, 2..12: token pairs in flight
__device__ __forceinline__ void run_chunk(
    float* hs, const float* __restrict__ W2ec, const float* __restrict__ Hme,
    float2 init, int s0cb, int rem, int tid, int c0,
    float* __restrict__ pm)
{
    unsigned long long a0[P], a1[P];
    unsigned long long i0 = splat2(init.x), i1 = splat2(init.y);
    #pragma unroll
    for (int p = 0; p < P; p++) { a0[p] = i0; a1[p] = i1; }

    __syncthreads();
    // stage h transposed: hs[kk*HSS + tk], tk in [0, 2P); Hme pre-offset kh*KC
    #pragma unroll
    for (int tk = 0; tk < 2 * P; tk++) {
        int slot = min(s0cb + tk, NTOK - 1); // clamp pad (discarded later)
        const float* src = Hme + (size_t)slot * (4 * HID);
        #pragma unroll
        for (int kk = 0; kk < KC; kk += 128)
            hs[(kk + tid) * HSS + tk] = src[kk + tid];
    }
    __syncthreads();

    float2 wA[WD], wB[WD];
    #pragma unroll
    for (int j = 0; j < WD; j++)
        wA[j] = __ldcs((const float2*)(W2ec + (size_t)j * EMB));

    #pragma unroll 1
    for (int g = 0; g < KC - 2 * WD; g += 2 * WD) {
        #pragma unroll
        for (int j = 0; j < WD; j++)
            wB[j] = __ldcs((const float2*)(W2ec + (size_t)(g + WD + j) * EMB));
        consume<P>(wA, hs, g, a0, a1);
        #pragma unroll
        for (int j = 0; j < WD; j++)
            wA[j] = __ldcs((const float2*)(W2ec + (size_t)(g + 2 * WD + j) * EMB));
        consume<P>(wB, hs, g + WD, a0, a1);
    }
    #pragma unroll
    for (int j = 0; j < WD; j++)
        wB[j] = __ldcs((const float2*)(W2ec + (size_t)(KC - WD + j) * EMB));
    consume<P>(wA, hs, KC - 2 * WD, a0, a1);
    consume<P>(wB, hs, KC - WD, a0, a1);

    #pragma unroll
    for (int p = 0; p < P; p++) {
        float2 vA = *(float2*)&a0[p]; // col c0:   (tok 2p, tok 2p+1)
        float2 vB = *(float2*)&a1[p]; // col c0+1
        int t0 = 2 * p;
        if (t0 < rem) {
            int slot = s0cb + t0;
            *(float2*)&pm[(size_t)slot * EMB + c0] = make_float2(vA.x, vB.x);
        }
        if (t0 + 1 < rem) {
            int slot = s0cb + t0 + 1;
            *(float2*)&pm[(size_t)slot * EMB + c0] = make_float2(vA.y, vB.y);
        }
    }
}

__global__ void __launch_bounds__(128, 4) k_stage2(Params p) {
    int bx   = blockIdx.x;     // 0..7 = tile(0..3) | kh<<2
    int tile = bx & 3;
    int kh   = bx >> 2;        // k-half: W2 rows [kh*256, +256)
    int m    = blockIdx.y;     // 0..3
    int e    = blockIdx.z;     // 0..31
    int s0 = g_start[e];
    int n  = g_start[e + 1] - s0;
    if (n == 0) return;

    int tid = threadIdx.x;
    int c0 = tile * 256 + tid * 2;
    const float* __restrict__ W2ec = p.W2[m] + (size_t)e * HID * EMB
                                   + (size_t)kh * KC * EMB + c0;
    const float* __restrict__ Hme  = g_H + m * HID + kh * KC;
    float2 init = (kh == 0)
        ? make_float2(p.b2[m][e * EMB + c0]     + p.te[m][c0],
                      p.b2[m][e * EMB + c0 + 1] + p.te[m][c0 + 1])
        : make_float2(0.f, 0.f);
    float* pm = &g_part[kh][(size_t)m * NTOK * EMB];

    __shared__ __align__(16) float hs[KC * HSS];

    for (int cb = 0; cb < n; cb += CHT) {
        int rem = min(n - cb, CHT);
        int pairsEven = ((rem + 3) >> 2) << 1; // even ceil(rem/2)
        int s0cb = s0 + cb;
        switch (pairsEven) {
#define CASE(PP) case PP: run_chunk<PP>(hs, W2ec, Hme, init, s0cb, rem, tid, c0, pm); break;
            CASE(2) CASE(4) CASE(6) CASE(8) CASE(10) CASE(12)
#undef CASE
        }
    }
}

// ---------------------------------------------------------------------------
// Combine: out[tok][m][c] = part0 + part1, gathering slot -> token.
// ---------------------------------------------------------------------------
__global__ void __launch_bounds__(256) k_combine(float* __restrict__ out) {
    int slot = blockIdx.x;
    int m    = blockIdx.y;
    int tid  = threadIdx.x;
    int tok  = g_tokens[slot];
    const float4* p0 = (const float4*)(&g_part[0][0] + ((size_t)m * NTOK + slot) * EMB);
    const float4* p1 = (const float4*)(&g_part[1][0] + ((size_t)m * NTOK + slot) * EMB);
    float4* o = (float4*)(out + ((size_t)tok * 4 + m) * EMB);
    float4 a = p0[tid], b = p1[tid];
    o[tid] = make_float4(a.x + b.x, a.y + b.y, a.z + b.z, a.w + b.w);
}

// ---------------------------------------------------------------------------
extern "C" void kernel_launch(void* const* d_in, const int* in_sizes, int n_in,
                              void* d_out, int out_size) {
    const float* state = (const float*)d_in[0];
    const int*   ids   = (const int*)d_in[1];

    Params P;
    int base = 2;
    for (int m = 0; m < 4; m++) {
        P.W1[m] = (const float*)d_in[base + 0];
        P.b1[m] = (const float*)d_in[base + 1];
        P.W2[m] = (const float*)d_in[base + 2];
        P.b2[m] = (const float*)d_in[base + 3];
        P.te[m] = (const float*)d_in[base + 4];
        base += 5;
    }
    float* out = (float*)d_out;

    k_stage1<<<128, 512>>>(state, ids, P);
    k_stage2<<<dim3(8, 4, 32), 128>>>(P);
    k_combine<<<dim3(NTOK, 4), 256>>>(out);
}

// round 14
// speedup vs baseline: 1.3922x; 1.0212x over previous
#include <cuda_runtime.h>

#define NTOK 512
#define DSTATE 192
#define HID 512
#define EMB 1024
#define NEMB 32
#define KC 256   // K rows per stage2 block (HID / 2 k-halves)
#define CHT 24   // tokens per stage2 chunk (P <= 12 pairs)
#define HSS 28   // smem row stride (floats): 112 B rows, 16B-aligned

// scratch (allocs forbidden -> device globals)
__device__ int g_start[NEMB + 1];
__device__ int g_tokens[NTOK];
__device__ float g_H[NTOK * 4 * HID];  // [slot][m][HID]

struct Params {
    const float* W1[4];
    const float* b1[4];
    const float* W2[4];
    const float* b2[4];
    const float* te[4];
};

// ---------------------------------------------------------------------------
// Stage 1 (exact round-9 champion): 128 blocks = (e,m), 512 threads.
// Deterministic match/histogram grouping (input-only -> identical per block);
// block 0 publishes for stage2. H[slot][m][:] = relu(x . W1[e] + b1[e]).
// ---------------------------------------------------------------------------
template <int L, int OFF>
__device__ __forceinline__ void mlp1(const float* __restrict__ state,
                                     const float* __restrict__ W1,
                                     float b, int m, int s0, int n,
                                     const int* __restrict__ s_tokens,
                                     float* __restrict__ xs) {
    int j = threadIdx.x;
    for (int cb = 0; cb < n; cb += 16) {
        int rem = min(n - cb, 16);
        __syncthreads();
        for (int idx = j; idx < 16 * L; idx += 512) {
            int tk = idx / L, l = idx % L;
            float v = 0.f;
            if (tk < rem) {
                int tok = s_tokens[s0 + cb + tk];
                v = state[tok * DSTATE + OFF + l];
            }
            xs[tk * L + l] = v;
        }
        __syncthreads();

        float acc[16];
        #pragma unroll
        for (int t = 0; t < 16; t++) acc[t] = b;

        #pragma unroll 1
        for (int l0 = 0; l0 < L; l0 += 8) {
            float w[8];
            #pragma unroll
            for (int u = 0; u < 8; u++)
                w[u] = W1[(l0 + u) * HID + j];
            #pragma unroll
            for (int u = 0; u < 8; u++) {
                #pragma unroll
                for (int t = 0; t < 16; t++)
                    acc[t] = fmaf(xs[t * L + l0 + u], w[u], acc[t]);
            }
        }

        #pragma unroll
        for (int t = 0; t < 16; t++) {
            if (t < rem)
                g_H[((size_t)(s0 + cb + t) * 4 + m) * HID + j] = fmaxf(acc[t], 0.f);
        }
        __syncthreads();
    }
}

__global__ void __launch_bounds__(512) k_stage1(const float* __restrict__ state,
                                                const int* __restrict__ ids_raw,
                                                Params p) {
    __shared__ int s_startA[NEMB + 1];
    __shared__ int s_tokens[NTOK];
    __shared__ int s_wcnt[16 * NEMB];
    __shared__ int s_woff[16 * NEMB];
    __shared__ int s_i64;
    __shared__ float xs[16 * 64];

    int tid  = threadIdx.x; // 512
    int warp = tid >> 5, lane = tid & 31;

    s_wcnt[tid & (16 * NEMB - 1)] = 0;
    if (tid == 0) s_i64 = 1;
    __syncthreads();
    if (tid < 256 && ids_raw[2 * tid + 1] != 0) s_i64 = 0;
    __syncthreads();
    int myc = s_i64 ? ids_raw[2 * tid] : ids_raw[tid];

    unsigned same = __match_any_sync(0xffffffffu, myc);
    int rankw = __popc(same & ((1u << lane) - 1u));
    if (rankw == 0) s_wcnt[warp * NEMB + myc] = __popc(same);
    __syncthreads();

    if (tid < NEMB) {
        int sum = 0;
        #pragma unroll
        for (int w = 0; w < 16; w++) {
            int ccc = s_wcnt[w * NEMB + tid];
            s_woff[w * NEMB + tid] = sum;
            sum += ccc;
        }
        s_wcnt[tid] = sum; // total per id
    }
    __syncthreads();
    if (tid <= NEMB) {
        int s = 0;
        for (int jj = 0; jj < tid && jj < NEMB; jj++) s += s_wcnt[jj];
        s_startA[tid] = s;
    }
    __syncthreads();

    int slot = s_startA[myc] + s_woff[warp * NEMB + myc] + rankw;
    s_tokens[slot] = tid;
    __syncthreads();

    if (blockIdx.x == 0) {
        if (tid <= NEMB) g_start[tid] = s_startA[tid];
        g_tokens[tid] = s_tokens[tid];
    }

    // ---- per-block MLP
    int m = blockIdx.x & 3;
    int e = blockIdx.x >> 2;
    int s0 = s_startA[e];
    int n  = s_startA[e + 1] - s0;
    if (n == 0) return;

    float b;
    switch (m) {
        case 0: b = p.b1[0][e * HID + tid];
                mlp1<64, 0  >(state, p.W1[0] + (size_t)e * 64 * HID, b, 0, s0, n, s_tokens, xs); break;
        case 1: b = p.b1[1][e * HID + tid];
                mlp1<64, 64 >(state, p.W1[1] + (size_t)e * 64 * HID, b, 1, s0, n, s_tokens, xs); break;
        case 2: b = p.b1[2][e * HID + tid];
                mlp1<32, 128>(state, p.W1[2] + (size_t)e * 32 * HID, b, 2, s0, n, s_tokens, xs); break;
        case 3: b = p.b1[3][e * HID + tid];
                mlp1<32, 160>(state, p.W1[3] + (size_t)e * 32 * HID, b, 3, s0, n, s_tokens, xs); break;
    }
}

// ---------------------------------------------------------------------------
// Stage 2 (K-split, atomic epilogue): each kh-half atomicAdds its partial
// (kh0 also carries bias+te) straight into the zero-initialized out.
// Exactly two commutative adds per element -> bitwise deterministic.
// Mainloop byte-identical to the round-8/9 champion.
// ---------------------------------------------------------------------------
__device__ __forceinline__ void fma2(unsigned long long& acc,
                                     unsigned long long h2,
                                     unsigned long long w2) {
    asm("fma.rn.f32x2 %0, %1, %2, %0;" : "+l"(acc) : "l"(h2), "l"(w2));
}
__device__ __forceinline__ unsigned long long splat2(float v) {
    unsigned long long r;
    asm("mov.b64 %0, {%1,%1};" : "=l"(r) : "r"(__float_as_uint(v)));
    return r;
}

#define WD 8  // W2 prefetch group size (LDG.64 each -> 16 lines/warp)

template <int P>
__device__ __forceinline__ void consume(const float2* w, const float* hs, int g,
                                        unsigned long long* a0, unsigned long long* a1) {
    #pragma unroll
    for (int j = 0; j < WD; j++) {
        unsigned long long w0 = splat2(w[j].x);
        unsigned long long w1 = splat2(w[j].y);
        const float* hrow = hs + (g + j) * HSS;
        #pragma unroll
        for (int p2 = 0; p2 < P / 2; p2++) {
            ulonglong2 hv = *(const ulonglong2*)(hrow + 4 * p2); // LDS.128 bcast
            fma2(a0[2 * p2],     hv.x, w0);
            fma2(a0[2 * p2 + 1], hv.y, w0);
            fma2(a1[2 * p2],     hv.x, w1);
            fma2(a1[2 * p2 + 1], hv.y, w1);
        }
    }
}

template <int P>  // P even, 2..12: token pairs in flight
__device__ __forceinline__ void run_chunk(
    float* hs, const float* __restrict__ W2ec, const float* __restrict__ Hme,
    float2 init, int s0cb, int rem, int tid, int c0, int m,
    float* __restrict__ out)
{
    unsigned long long a0[P], a1[P];
    unsigned long long i0 = splat2(init.x), i1 = splat2(init.y);
    #pragma unroll
    for (int p = 0; p < P; p++) { a0[p] = i0; a1[p] = i1; }

    __syncthreads();
    // stage h transposed: hs[kk*HSS + tk], tk in [0, 2P); Hme pre-offset kh*KC
    #pragma unroll
    for (int tk = 0; tk < 2 * P; tk++) {
        int slot = min(s0cb + tk, NTOK - 1); // clamp pad (discarded later)
        const float* src = Hme + (size_t)slot * (4 * HID);
        #pragma unroll
        for (int kk = 0; kk < KC; kk += 128)
            hs[(kk + tid) * HSS + tk] = src[kk + tid];
    }
    __syncthreads();

    float2 wA[WD], wB[WD];
    #pragma unroll
    for (int j = 0; j < WD; j++)
        wA[j] = __ldcs((const float2*)(W2ec + (size_t)j * EMB));

    #pragma unroll 1
    for (int g = 0; g < KC - 2 * WD; g += 2 * WD) {
        #pragma unroll
        for (int j = 0; j < WD; j++)
            wB[j] = __ldcs((const float2*)(W2ec + (size_t)(g + WD + j) * EMB));
        consume<P>(wA, hs, g, a0, a1);
        #pragma unroll
        for (int j = 0; j < WD; j++)
            wA[j] = __ldcs((const float2*)(W2ec + (size_t)(g + 2 * WD + j) * EMB));
        consume<P>(wB, hs, g + WD, a0, a1);
    }
    #pragma unroll
    for (int j = 0; j < WD; j++)
        wB[j] = __ldcs((const float2*)(W2ec + (size_t)(KC - WD + j) * EMB));
    consume<P>(wA, hs, KC - 2 * WD, a0, a1);
    consume<P>(wB, hs, KC - WD, a0, a1);

    // ---- atomic epilogue: out was memset to 0; two commutative adds/elem ----
    #pragma unroll
    for (int p = 0; p < P; p++) {
        float2 vA = *(float2*)&a0[p]; // col c0:   (tok 2p, tok 2p+1)
        float2 vB = *(float2*)&a1[p]; // col c0+1
        int t0 = 2 * p;
        if (t0 < rem) {
            int tok = g_tokens[s0cb + t0];
            float* dst = &out[((size_t)tok * 4 + m) * EMB + c0];
            atomicAdd(dst,     vA.x);
            atomicAdd(dst + 1, vB.x);
        }
        if (t0 + 1 < rem) {
            int tok = g_tokens[s0cb + t0 + 1];
            float* dst = &out[((size_t)tok * 4 + m) * EMB + c0];
            atomicAdd(dst,     vA.y);
            atomicAdd(dst + 1, vB.y);
        }
    }
}

__global__ void __launch_bounds__(128, 4) k_stage2(Params p, float* __restrict__ out) {
    int bx   = blockIdx.x;     // 0..7 = tile(0..3) | kh<<2
    int tile = bx & 3;
    int kh   = bx >> 2;        // k-half: W2 rows [kh*256, +256)
    int m    = blockIdx.y;     // 0..3
    int e    = blockIdx.z;     // 0..31
    int s0 = g_start[e];
    int n  = g_start[e + 1] - s0;
    if (n == 0) return;

    int tid = threadIdx.x;
    int c0 = tile * 256 + tid * 2;
    const float* __restrict__ W2ec = p.W2[m] + (size_t)e * HID * EMB
                                   + (size_t)kh * KC * EMB + c0;
    const float* __restrict__ Hme  = g_H + m * HID + kh * KC;
    float2 init = (kh == 0)
        ? make_float2(p.b2[m][e * EMB + c0]     + p.te[m][c0],
                      p.b2[m][e * EMB + c0 + 1] + p.te[m][c0 + 1])
        : make_float2(0.f, 0.f);

    __shared__ __align__(16) float hs[KC * HSS];

    for (int cb = 0; cb < n; cb += CHT) {
        int rem = min(n - cb, CHT);
        int pairsEven = ((rem + 3) >> 2) << 1; // even ceil(rem/2)
        int s0cb = s0 + cb;
        switch (pairsEven) {
#define CASE(PP) case PP: run_chunk<PP>(hs, W2ec, Hme, init, s0cb, rem, tid, c0, m, out); break;
            CASE(2) CASE(4) CASE(6) CASE(8) CASE(10) CASE(12)
#undef CASE
        }
    }
}

// ---------------------------------------------------------------------------
extern "C" void kernel_launch(void* const* d_in, const int* in_sizes, int n_in,
                              void* d_out, int out_size) {
    const float* state = (const float*)d_in[0];
    const int*   ids   = (const int*)d_in[1];

    Params P;
    int base = 2;
    for (int m = 0; m < 4; m++) {
        P.W1[m] = (const float*)d_in[base + 0];
        P.b1[m] = (const float*)d_in[base + 1];
        P.W2[m] = (const float*)d_in[base + 2];
        P.b2[m] = (const float*)d_in[base + 3];
        P.te[m] = (const float*)d_in[base + 4];
        base += 5;
    }
    float* out = (float*)d_out;

    // zero-init output (graph-capturable memset node; atomics accumulate on it)
    cudaMemsetAsync(out, 0, (size_t)out_size * sizeof(float));

    k_stage1<<<128, 512>>>(state, ids, P);
    k_stage2<<<dim3(8, 4, 32), 128>>>(P, out);
}